// round 8
// baseline (speedup 1.0000x reference)
#include <cuda_runtime.h>
#include <cuda_fp16.h>
#include <cstdint>
#include <cstddef>

#define N_NODES 8192
#define DIN     512
#define DOUT    256
#define ALPHA   0.2f
#define NEG_INF -9e15f
#define L2E     1.4426950408889634f

// ---------------- scratch (device globals; no allocations allowed) ----------
__device__ float  g_Wh [(size_t)N_NODES * DOUT];   // 8 MB fp32 row-major (k2)
__device__ __half g_Whh[(size_t)N_NODES * DOUT];   // 4 MB fp16 row-major (k4 B)
__device__ float g_src[N_NODES];
__device__ float g_dst[N_NODES];
__device__ float g_rmax[N_NODES];
__device__ float g_rsum[N_NODES];

// ---------------- helpers ----------------------------------------------------
__device__ __forceinline__ uint32_t smem_u32(const void* p) {
    uint32_t a;
    asm("{ .reg .u64 t; cvta.to.shared.u64 t, %1; cvt.u32.u64 %0, t; }"
        : "=r"(a) : "l"(p));
    return a;
}

__device__ __forceinline__ void ldmx4(uint32_t* r, uint32_t addr) {
    asm volatile("ldmatrix.sync.aligned.m8n8.x4.shared.b16 {%0,%1,%2,%3}, [%4];"
                 : "=r"(r[0]), "=r"(r[1]), "=r"(r[2]), "=r"(r[3]) : "r"(addr));
}
__device__ __forceinline__ void ldmx4t(uint32_t* r, uint32_t addr) {
    asm volatile("ldmatrix.sync.aligned.m8n8.x4.trans.shared.b16 {%0,%1,%2,%3}, [%4];"
                 : "=r"(r[0]), "=r"(r[1]), "=r"(r[2]), "=r"(r[3]) : "r"(addr));
}
__device__ __forceinline__ void mma16816(float* c, const uint32_t* a,
                                         uint32_t b0, uint32_t b1) {
    asm volatile(
        "mma.sync.aligned.m16n8k16.row.col.f32.f16.f16.f32 "
        "{%0,%1,%2,%3}, {%4,%5,%6,%7}, {%8,%9}, {%0,%1,%2,%3};\n"
        : "+f"(c[0]), "+f"(c[1]), "+f"(c[2]), "+f"(c[3])
        : "r"(a[0]), "r"(a[1]), "r"(a[2]), "r"(a[3]), "r"(b0), "r"(b1));
}

__device__ __forceinline__ void cp_async16(uint32_t smem_addr, const void* gptr) {
    asm volatile("cp.async.cg.shared.global [%0], [%1], 16;\n"
                 :: "r"(smem_addr), "l"(gptr));
}
__device__ __forceinline__ void cp_commit() {
    asm volatile("cp.async.commit_group;\n" ::: "memory");
}
template <int N>
__device__ __forceinline__ void cp_wait() {
    asm volatile("cp.async.wait_group %0;\n" :: "n"(N) : "memory");
}

// ---------------- K1: Wh = X @ W  (fp32, tiled; also emits fp16 copy) --------
__global__ void __launch_bounds__(256) k1_gemm(const float* __restrict__ X,
                                               const float* __restrict__ W) {
    __shared__ float As[16][68];
    __shared__ float Bs[16][68];
    int t  = threadIdx.x;
    int tx = t & 15, ty = t >> 4;
    int m0 = blockIdx.x * 64, n0 = blockIdx.y * 64;

    float acc[4][4];
    #pragma unroll
    for (int i = 0; i < 4; i++)
        #pragma unroll
        for (int j = 0; j < 4; j++) acc[i][j] = 0.f;

    for (int k0 = 0; k0 < DIN; k0 += 16) {
        {
            int row = t >> 2, c4 = (t & 3) * 4;
            float4 v = *(const float4*)&X[(size_t)(m0 + row) * DIN + k0 + c4];
            As[c4 + 0][row] = v.x; As[c4 + 1][row] = v.y;
            As[c4 + 2][row] = v.z; As[c4 + 3][row] = v.w;
        }
        {
            int row = t >> 4, c4 = (t & 15) * 4;
            *(float4*)&Bs[row][c4] = *(const float4*)&W[(size_t)(k0 + row) * DOUT + n0 + c4];
        }
        __syncthreads();
        #pragma unroll
        for (int k = 0; k < 16; k++) {
            float4 a4 = *(float4*)&As[k][ty * 4];
            float4 b4 = *(float4*)&Bs[k][tx * 4];
            float av[4] = {a4.x, a4.y, a4.z, a4.w};
            float bv[4] = {b4.x, b4.y, b4.z, b4.w};
            #pragma unroll
            for (int i = 0; i < 4; i++)
                #pragma unroll
                for (int j = 0; j < 4; j++) acc[i][j] += av[i] * bv[j];
        }
        __syncthreads();
    }
    #pragma unroll
    for (int i = 0; i < 4; i++) {
        size_t base = (size_t)(m0 + ty * 4 + i) * DOUT + n0 + tx * 4;
        float4 v = make_float4(acc[i][0], acc[i][1], acc[i][2], acc[i][3]);
        *(float4*)&g_Wh[base] = v;
        __half2 h0 = __floats2half2_rn(acc[i][0], acc[i][1]);
        __half2 h1 = __floats2half2_rn(acc[i][2], acc[i][3]);
        *(__half2*)&g_Whh[base]     = h0;
        *(__half2*)&g_Whh[base + 2] = h1;
    }
}

// ---------------- K2: src/dst projections (warp per row) ---------------------
__global__ void __launch_bounds__(256) k2_srcdst(const float* __restrict__ a) {
    int lane = threadIdx.x & 31, w = threadIdx.x >> 5;
    int i = blockIdx.x * 8 + w;
    float s1 = 0.f, s2 = 0.f;
    #pragma unroll
    for (int c = lane; c < DOUT; c += 32) {
        float wh = g_Wh[(size_t)i * DOUT + c];
        s1 += wh * a[c];
        s2 += wh * a[DOUT + c];
    }
    #pragma unroll
    for (int o = 16; o > 0; o >>= 1) {
        s1 += __shfl_xor_sync(0xffffffffu, s1, o);
        s2 += __shfl_xor_sync(0xffffffffu, s2, o);
    }
    if (lane == 0) { g_src[i] = s1; g_dst[i] = s2; }
}

// ---------------- K3: per-row max and sum(exp(e - m)) ------------------------
__global__ void __launch_bounds__(256) k3_rowstats(const int* __restrict__ adj) {
    int i = blockIdx.x;
    int t = threadIdx.x;
    int lane = t & 31, w = t >> 5;
    __shared__ float red[8];
    __shared__ float bcast;

    float si = g_src[i];
    float ev[32];
    float mx = NEG_INF;
    #pragma unroll
    for (int s = 0; s < 8; s++) {
        int j = (s * 256 + t) * 4;
        int4   a4 = *(const int4*)&adj[(size_t)i * N_NODES + j];
        float4 d4 = *(const float4*)&g_dst[j];
        float xs[4] = {si + d4.x, si + d4.y, si + d4.z, si + d4.w};
        int   am[4] = {a4.x, a4.y, a4.z, a4.w};
        #pragma unroll
        for (int c = 0; c < 4; c++) {
            float x = xs[c];
            float e = fmaxf(x, ALPHA * x);
            e = (am[c] > 0) ? e : NEG_INF;
            ev[s * 4 + c] = e;
            mx = fmaxf(mx, e);
        }
    }
    #pragma unroll
    for (int o = 16; o > 0; o >>= 1) mx = fmaxf(mx, __shfl_xor_sync(0xffffffffu, mx, o));
    if (lane == 0) red[w] = mx;
    __syncthreads();
    if (t == 0) {
        float m2 = red[0];
        #pragma unroll
        for (int q = 1; q < 8; q++) m2 = fmaxf(m2, red[q]);
        bcast = m2;
    }
    __syncthreads();
    float bm = bcast;

    float sum = 0.f;
    #pragma unroll
    for (int q = 0; q < 32; q++) sum += __expf(ev[q] - bm);
    #pragma unroll
    for (int o = 16; o > 0; o >>= 1) sum += __shfl_xor_sync(0xffffffffu, sum, o);
    __syncthreads();
    if (lane == 0) red[w] = sum;
    __syncthreads();
    if (t == 0) {
        float s2 = 0.f;
        #pragma unroll
        for (int q = 0; q < 8; q++) s2 += red[q];
        g_rmax[i] = bm;
        g_rsum[i] = s2;
    }
}

// ---------------- K4: h' = softmax(P) @ Wh, fp16 mma + ldmatrix --------------
// Grid (4, 128): x = 64-col tile (fastest -> adj L2 reuse), y = 64-row tile.
// Block 256 = 8 warps (mi = w&1 over 32-row halves, nj = w>>1 over 16-col
// quarters). K-tile 32 = 2 x m16n8k16 steps. P: 64x32 fp16, stride 80B
// (conflict-free ldmatrix via r*5 mod 8). Wh: 32x64 fp16, 128B rows with
// chunk swizzle c^(r&7). Double-buffered, one barrier per tile.
#define KT   32
#define NIT  (N_NODES / KT)

__global__ void __launch_bounds__(256, 3) k4_attn(const int* __restrict__ adj,
                                                  float* __restrict__ out) {
    __shared__ __align__(16) char whsm[2][4096];   // [stage][32 rows][8 chunks]
    __shared__ __align__(16) char psm [2][5120];   // [stage][64 rows][80B]
    __shared__ float src_s[64], m2_s[64], linv_s[64];

    int t    = threadIdx.x;
    int lane = t & 31, w = t >> 5;
    int mi = w & 1;          // 32-row half
    int nj = w >> 1;         // 16-col quarter
    int J0 = blockIdx.x * 64;
    int I0 = blockIdx.y * 64;

    if (t < 64) {
        src_s[t]  = g_src[I0 + t];
        m2_s[t]   = g_rmax[I0 + t] * L2E;
        linv_s[t] = 1.0f / g_rsum[I0 + t];
    }

    float acc[2][2][4];
    #pragma unroll
    for (int i = 0; i < 2; i++)
        #pragma unroll
        for (int j = 0; j < 2; j++)
            #pragma unroll
            for (int q = 0; q < 4; q++) acc[i][j][q] = 0.f;

    // ---- builder mapping: thread -> row rb = t>>2, k-chunk kc8 = (t&3)*8 ----
    int rb  = t >> 2;
    int kc8 = (t & 3) * 8;
    const int* adjrow = adj + (size_t)(I0 + rb) * N_NODES + kc8;

    // ---- Wh cp.async mapping: row wr = t>>3, chunk wc = t&7 (swizzled) ------
    int wr = t >> 3, wc = t & 7;
    uint32_t wh_dst0 = smem_u32(&whsm[0][0]) + wr * 128 + ((wc ^ (wr & 7)) * 16);
    const __half* wh_src_base = &g_Whh[(size_t)wr * DOUT + J0 + wc * 8];

    // ---- ldmatrix lane address components ----
    uint32_t pbase0  = smem_u32(&psm[0][0]);
    uint32_t whbase0 = smem_u32(&whsm[0][0]);
    int rowA = (lane & 7) + ((lane >> 3) & 1) * 8;       // row within i-tile
    int kxA  = lane >> 4;                                // k-chunk select
    uint32_t aAddr0 = pbase0 + (mi * 32 + rowA) * 80 + kxA * 16;
    int rowB = (lane & 7) + ((lane >> 3) & 1) * 8;       // k-row within tile
    int cswzB = (nj * 2 + (lane >> 4)) ^ (lane & 7);     // swizzled n-chunk
    uint32_t bAddr0 = whbase0 + rowB * 128 + cswzB * 16;

    // ---- prologue ----
    // Wh stage 0
    cp_async16(wh_dst0, wh_src_base);
    cp_commit();
    // adj tile 0 -> regs
    int4 aj0 = *(const int4*)&adjrow[0];
    int4 aj1 = *(const int4*)&adjrow[4];

    __syncthreads();    // stats visible

    // build P[0]
    {
        float sv = src_s[rb], mt2 = m2_s[rb];
        float4 d0 = *(const float4*)&g_dst[kc8];
        float4 d1 = *(const float4*)&g_dst[kc8 + 4];
        float xs[8] = {sv + d0.x, sv + d0.y, sv + d0.z, sv + d0.w,
                       sv + d1.x, sv + d1.y, sv + d1.z, sv + d1.w};
        int   am[8] = {aj0.x, aj0.y, aj0.z, aj0.w, aj1.x, aj1.y, aj1.z, aj1.w};
        float p[8];
        #pragma unroll
        for (int c = 0; c < 8; c++) {
            float x = xs[c];
            float e = fmaxf(x, ALPHA * x);
            e = (am[c] > 0) ? e : NEG_INF;
            p[c] = exp2f(fmaf(e, L2E, -mt2));
        }
        __half2 h0 = __floats2half2_rn(p[0], p[1]);
        __half2 h1 = __floats2half2_rn(p[2], p[3]);
        __half2 h2 = __floats2half2_rn(p[4], p[5]);
        __half2 h3 = __floats2half2_rn(p[6], p[7]);
        uint4 v;
        v.x = *(uint32_t*)&h0; v.y = *(uint32_t*)&h1;
        v.z = *(uint32_t*)&h2; v.w = *(uint32_t*)&h3;
        *(uint4*)&psm[0][rb * 80 + (t & 3) * 16] = v;
    }
    // prefetch adj tile 1
    aj0 = *(const int4*)&adjrow[KT];
    aj1 = *(const int4*)&adjrow[KT + 4];

    for (int it = 0; it < NIT; ++it) {
        int cur = it & 1;
        int nxt = cur ^ 1;
        bool more = (it + 1 < NIT);

        cp_wait<0>();
        __syncthreads();   // publishes stage cur; retires all reads of nxt

        if (more) {
            int kn = (it + 1) * KT;
            // Wh[nxt]
            cp_async16(wh_dst0 + nxt * 4096,
                       wh_src_base + (size_t)kn * DOUT);
            cp_commit();

            // build P[nxt] (tile it+1)
            {
                float sv = src_s[rb], mt2 = m2_s[rb];
                float4 d0 = *(const float4*)&g_dst[kn + kc8];
                float4 d1 = *(const float4*)&g_dst[kn + kc8 + 4];
                float xs[8] = {sv + d0.x, sv + d0.y, sv + d0.z, sv + d0.w,
                               sv + d1.x, sv + d1.y, sv + d1.z, sv + d1.w};
                int   am[8] = {aj0.x, aj0.y, aj0.z, aj0.w,
                               aj1.x, aj1.y, aj1.z, aj1.w};
                float p[8];
                #pragma unroll
                for (int c = 0; c < 8; c++) {
                    float x = xs[c];
                    float e = fmaxf(x, ALPHA * x);
                    e = (am[c] > 0) ? e : NEG_INF;
                    p[c] = exp2f(fmaf(e, L2E, -mt2));
                }
                __half2 h0 = __floats2half2_rn(p[0], p[1]);
                __half2 h1 = __floats2half2_rn(p[2], p[3]);
                __half2 h2 = __floats2half2_rn(p[4], p[5]);
                __half2 h3 = __floats2half2_rn(p[6], p[7]);
                uint4 v;
                v.x = *(uint32_t*)&h0; v.y = *(uint32_t*)&h1;
                v.z = *(uint32_t*)&h2; v.w = *(uint32_t*)&h3;
                *(uint4*)&psm[nxt][rb * 80 + (t & 3) * 16] = v;
            }

            // prefetch adj for tile it+2
            if (it + 2 < NIT) {
                const int* ab = adjrow + (it + 2) * KT;
                aj0 = *(const int4*)&ab[0];
                aj1 = *(const int4*)&ab[4];
            }
        }

        // ---- MMA on stage cur ----
        {
            uint32_t aAddr = aAddr0 + cur * 5120;
            uint32_t bAddr = bAddr0 + cur * 4096;
            #pragma unroll
            for (int ks = 0; ks < 2; ks++) {
                uint32_t b[4];
                ldmx4t(b, bAddr + ks * 2048);            // 16 k-rows
                #pragma unroll
                for (int itile = 0; itile < 2; itile++) {
                    uint32_t a[4];
                    ldmx4(a, aAddr + itile * 1280 + ks * 32);
                    mma16816(acc[itile][0], a, b[0], b[1]);
                    mma16816(acc[itile][1], a, b[2], b[3]);
                }
            }
        }
    }

    // ---- epilogue: /rowsum, ELU, store ----
    #pragma unroll
    for (int itile = 0; itile < 2; itile++) {
        int r0 = mi * 32 + itile * 16 + (lane >> 2);
        float l0 = linv_s[r0], l1 = linv_s[r0 + 8];
        #pragma unroll
        for (int nb = 0; nb < 2; nb++) {
            int c = J0 + nj * 16 + nb * 8 + (lane & 3) * 2;
            float v0 = acc[itile][nb][0] * l0;
            float v1 = acc[itile][nb][1] * l0;
            float v2 = acc[itile][nb][2] * l1;
            float v3 = acc[itile][nb][3] * l1;
            float2 lo, hi;
            lo.x = (v0 > 0.f) ? v0 : expm1f(v0);
            lo.y = (v1 > 0.f) ? v1 : expm1f(v1);
            hi.x = (v2 > 0.f) ? v2 : expm1f(v2);
            hi.y = (v3 > 0.f) ? v3 : expm1f(v3);
            *(float2*)&out[(size_t)(I0 + r0)     * DOUT + c] = lo;
            *(float2*)&out[(size_t)(I0 + r0 + 8) * DOUT + c] = hi;
        }
    }
}

// ---------------- launch ------------------------------------------------------
extern "C" void kernel_launch(void* const* d_in, const int* in_sizes, int n_in,
                              void* d_out, int out_size) {
    const float* X   = (const float*)d_in[0];   // features [8192,512]
    const int*   adj = (const int*)  d_in[1];   // adj      [8192,8192]
    const float* W   = (const float*)d_in[2];   // W        [512,256]
    const float* a   = (const float*)d_in[3];   // a        [512,1]
    float* out = (float*)d_out;                 // [8192,256]

    k1_gemm    <<<dim3(N_NODES / 64, DOUT / 64), 256>>>(X, W);
    k2_srcdst  <<<N_NODES / 8, 256>>>(a);
    k3_rowstats<<<N_NODES, 256>>>(adj);
    k4_attn    <<<dim3(DOUT / 64, N_NODES / 64), 256>>>(adj, out);
}

// round 9
// speedup vs baseline: 1.5342x; 1.5342x over previous
#include <cuda_runtime.h>
#include <cuda_fp16.h>
#include <cstdint>
#include <cstddef>

#define N_NODES 8192
#define DIN     512
#define DOUT    256
#define ALPHA   0.2f
#define NEG_INF -9e15f
#define L2E     1.4426950408889634f

// ---------------- scratch (device globals; no allocations allowed) ----------
__device__ float  g_Wh [(size_t)N_NODES * DOUT];   // 8 MB fp32 row-major (k2)
__device__ __half g_Whh[(size_t)N_NODES * DOUT];   // 4 MB fp16 row-major (k4 B)
__device__ float g_src[N_NODES];
__device__ float g_dst[N_NODES];
__device__ float g_rmax[N_NODES];
__device__ float g_rsum[N_NODES];

// ---------------- helpers ----------------------------------------------------
__device__ __forceinline__ uint32_t smem_u32(const void* p) {
    uint32_t a;
    asm("{ .reg .u64 t; cvta.to.shared.u64 t, %1; cvt.u32.u64 %0, t; }"
        : "=r"(a) : "l"(p));
    return a;
}

__device__ __forceinline__ void ldmx4(uint32_t* r, uint32_t addr) {
    asm volatile("ldmatrix.sync.aligned.m8n8.x4.shared.b16 {%0,%1,%2,%3}, [%4];"
                 : "=r"(r[0]), "=r"(r[1]), "=r"(r[2]), "=r"(r[3]) : "r"(addr));
}
__device__ __forceinline__ void ldmx4t(uint32_t* r, uint32_t addr) {
    asm volatile("ldmatrix.sync.aligned.m8n8.x4.trans.shared.b16 {%0,%1,%2,%3}, [%4];"
                 : "=r"(r[0]), "=r"(r[1]), "=r"(r[2]), "=r"(r[3]) : "r"(addr));
}
__device__ __forceinline__ void mma16816(float* c, const uint32_t* a,
                                         uint32_t b0, uint32_t b1) {
    asm volatile(
        "mma.sync.aligned.m16n8k16.row.col.f32.f16.f16.f32 "
        "{%0,%1,%2,%3}, {%4,%5,%6,%7}, {%8,%9}, {%0,%1,%2,%3};\n"
        : "+f"(c[0]), "+f"(c[1]), "+f"(c[2]), "+f"(c[3])
        : "r"(a[0]), "r"(a[1]), "r"(a[2]), "r"(a[3]), "r"(b0), "r"(b1));
}

__device__ __forceinline__ void cp_async16(uint32_t smem_addr, const void* gptr) {
    asm volatile("cp.async.cg.shared.global [%0], [%1], 16;\n"
                 :: "r"(smem_addr), "l"(gptr));
}
__device__ __forceinline__ void cp_commit() {
    asm volatile("cp.async.commit_group;\n" ::: "memory");
}
template <int N>
__device__ __forceinline__ void cp_wait() {
    asm volatile("cp.async.wait_group %0;\n" :: "n"(N) : "memory");
}

// ---------------- K1: Wh = X @ W  (fp32, tiled; also emits fp16 copy) --------
__global__ void __launch_bounds__(256) k1_gemm(const float* __restrict__ X,
                                               const float* __restrict__ W) {
    __shared__ float As[16][68];
    __shared__ float Bs[16][68];
    int t  = threadIdx.x;
    int tx = t & 15, ty = t >> 4;
    int m0 = blockIdx.x * 64, n0 = blockIdx.y * 64;

    float acc[4][4];
    #pragma unroll
    for (int i = 0; i < 4; i++)
        #pragma unroll
        for (int j = 0; j < 4; j++) acc[i][j] = 0.f;

    for (int k0 = 0; k0 < DIN; k0 += 16) {
        {
            int row = t >> 2, c4 = (t & 3) * 4;
            float4 v = *(const float4*)&X[(size_t)(m0 + row) * DIN + k0 + c4];
            As[c4 + 0][row] = v.x; As[c4 + 1][row] = v.y;
            As[c4 + 2][row] = v.z; As[c4 + 3][row] = v.w;
        }
        {
            int row = t >> 4, c4 = (t & 15) * 4;
            *(float4*)&Bs[row][c4] = *(const float4*)&W[(size_t)(k0 + row) * DOUT + n0 + c4];
        }
        __syncthreads();
        #pragma unroll
        for (int k = 0; k < 16; k++) {
            float4 a4 = *(float4*)&As[k][ty * 4];
            float4 b4 = *(float4*)&Bs[k][tx * 4];
            float av[4] = {a4.x, a4.y, a4.z, a4.w};
            float bv[4] = {b4.x, b4.y, b4.z, b4.w};
            #pragma unroll
            for (int i = 0; i < 4; i++)
                #pragma unroll
                for (int j = 0; j < 4; j++) acc[i][j] += av[i] * bv[j];
        }
        __syncthreads();
    }
    #pragma unroll
    for (int i = 0; i < 4; i++) {
        size_t base = (size_t)(m0 + ty * 4 + i) * DOUT + n0 + tx * 4;
        float4 v = make_float4(acc[i][0], acc[i][1], acc[i][2], acc[i][3]);
        *(float4*)&g_Wh[base] = v;
        __half2 h0 = __floats2half2_rn(acc[i][0], acc[i][1]);
        __half2 h1 = __floats2half2_rn(acc[i][2], acc[i][3]);
        *(__half2*)&g_Whh[base]     = h0;
        *(__half2*)&g_Whh[base + 2] = h1;
    }
}

// ---------------- K2: src/dst projections (warp per row) ---------------------
__global__ void __launch_bounds__(256) k2_srcdst(const float* __restrict__ a) {
    int lane = threadIdx.x & 31, w = threadIdx.x >> 5;
    int i = blockIdx.x * 8 + w;
    float s1 = 0.f, s2 = 0.f;
    #pragma unroll
    for (int c = lane; c < DOUT; c += 32) {
        float wh = g_Wh[(size_t)i * DOUT + c];
        s1 += wh * a[c];
        s2 += wh * a[DOUT + c];
    }
    #pragma unroll
    for (int o = 16; o > 0; o >>= 1) {
        s1 += __shfl_xor_sync(0xffffffffu, s1, o);
        s2 += __shfl_xor_sync(0xffffffffu, s2, o);
    }
    if (lane == 0) { g_src[i] = s1; g_dst[i] = s2; }
}

// ---------------- K3: per-row max and sum(exp(e - m)) ------------------------
__global__ void __launch_bounds__(256) k3_rowstats(const int* __restrict__ adj) {
    int i = blockIdx.x;
    int t = threadIdx.x;
    int lane = t & 31, w = t >> 5;
    __shared__ float red[8];
    __shared__ float bcast;

    float si = g_src[i];
    float ev[32];
    float mx = NEG_INF;
    #pragma unroll
    for (int s = 0; s < 8; s++) {
        int j = (s * 256 + t) * 4;
        int4   a4 = *(const int4*)&adj[(size_t)i * N_NODES + j];
        float4 d4 = *(const float4*)&g_dst[j];
        float xs[4] = {si + d4.x, si + d4.y, si + d4.z, si + d4.w};
        int   am[4] = {a4.x, a4.y, a4.z, a4.w};
        #pragma unroll
        for (int c = 0; c < 4; c++) {
            float x = xs[c];
            float e = fmaxf(x, ALPHA * x);
            e = (am[c] > 0) ? e : NEG_INF;
            ev[s * 4 + c] = e;
            mx = fmaxf(mx, e);
        }
    }
    #pragma unroll
    for (int o = 16; o > 0; o >>= 1) mx = fmaxf(mx, __shfl_xor_sync(0xffffffffu, mx, o));
    if (lane == 0) red[w] = mx;
    __syncthreads();
    if (t == 0) {
        float m2 = red[0];
        #pragma unroll
        for (int q = 1; q < 8; q++) m2 = fmaxf(m2, red[q]);
        bcast = m2;
    }
    __syncthreads();
    float bm = bcast;

    float sum = 0.f;
    #pragma unroll
    for (int q = 0; q < 32; q++) sum += __expf(ev[q] - bm);
    #pragma unroll
    for (int o = 16; o > 0; o >>= 1) sum += __shfl_xor_sync(0xffffffffu, sum, o);
    __syncthreads();
    if (lane == 0) red[w] = sum;
    __syncthreads();
    if (t == 0) {
        float s2 = 0.f;
        #pragma unroll
        for (int q = 0; q < 8; q++) s2 += red[q];
        g_rmax[i] = bm;
        g_rsum[i] = s2;
    }
}

// ---------------- K4: h' = softmax(P) @ Wh, fp16 mma + ldmatrix --------------
// Grid (2, 128): x = 128-col half (fastest -> same-I CTAs adjacent, adj L2
// reuse), y = 64-row tile. Block 256 = 8 warps (mi = w&1 over 32-row halves,
// nj = w>>1 over 32-col quarters of the 128-col half). Warp tile 32x32.
// K-tile 32 = 2 x m16n8k16 steps. P: 64x32 fp16, row stride 80B (conflict-free
// ldmatrix, r*20 mod 32 distinct). Wh: 32x128 fp16, 256B rows, chunk swizzle
// c^(r&7). Double-buffered, one barrier per tile.
#define KT   32
#define NIT  (N_NODES / KT)

__global__ void __launch_bounds__(256, 2) k4_attn(const int* __restrict__ adj,
                                                  float* __restrict__ out) {
    __shared__ __align__(16) char whsm[2][8192];   // [stage][32 k-rows][256B]
    __shared__ __align__(16) char psm [2][5120];   // [stage][64 rows][80B]
    __shared__ float src_s[64], m2_s[64], linv_s[64];

    int t    = threadIdx.x;
    int lane = t & 31, w = t >> 5;
    int mi = w & 1;          // 32-row half
    int nj = w >> 1;         // 32-col quarter
    int J0 = blockIdx.x * 128;
    int I0 = blockIdx.y * 64;

    if (t < 64) {
        src_s[t]  = g_src[I0 + t];
        m2_s[t]   = g_rmax[I0 + t] * L2E;
        linv_s[t] = 1.0f / g_rsum[I0 + t];
    }

    float acc[2][4][4];
    #pragma unroll
    for (int i = 0; i < 2; i++)
        #pragma unroll
        for (int j = 0; j < 4; j++)
            #pragma unroll
            for (int q = 0; q < 4; q++) acc[i][j][q] = 0.f;

    // ---- builder mapping: row rb = t>>2, k-chunk kc8 = (t&3)*8 ----
    int rb  = t >> 2;
    int kc8 = (t & 3) * 8;
    const int* adjrow = adj + (size_t)(I0 + rb) * N_NODES + kc8;

    // ---- Wh cp.async mapping: row wr = t>>3, chunks c1, c1+8 (swizzled) -----
    int wr = t >> 3, c1 = t & 7;
    uint32_t wh_dst = smem_u32(&whsm[0][0]) + wr * 256 + ((c1 ^ (wr & 7)) * 16);
    const __half* wh_src = &g_Whh[(size_t)wr * DOUT + J0 + c1 * 8];

    // ---- ldmatrix lane address components ----
    uint32_t pbase  = smem_u32(&psm[0][0]);
    uint32_t whbase = smem_u32(&whsm[0][0]);
    int rowM = (lane & 7) + ((lane >> 3) & 1) * 8;       // 0..15 (lanes 16-31 repeat)
    uint32_t aAddr0 = pbase + (mi * 32 + rowM) * 80 + (lane >> 4) * 16;
    int cs0 = (nj * 4 + 0 + (lane >> 4)) ^ (lane & 7);
    int cs1 = (nj * 4 + 2 + (lane >> 4)) ^ (lane & 7);
    uint32_t bAddr0 = whbase + rowM * 256 + cs0 * 16;
    uint32_t bAddr1 = whbase + rowM * 256 + cs1 * 16;

    // ---- prologue ----
    cp_async16(wh_dst, wh_src);
    cp_async16(wh_dst + 128, wh_src + 64);
    cp_commit();
    int4 aj0 = *(const int4*)&adjrow[0];
    int4 aj1 = *(const int4*)&adjrow[4];

    __syncthreads();    // stats visible
    float sv  = src_s[rb];
    float mt2 = m2_s[rb];

    // build P[0]
    {
        float4 d0 = *(const float4*)&g_dst[kc8];
        float4 d1 = *(const float4*)&g_dst[kc8 + 4];
        float xs[8] = {sv + d0.x, sv + d0.y, sv + d0.z, sv + d0.w,
                       sv + d1.x, sv + d1.y, sv + d1.z, sv + d1.w};
        int   am[8] = {aj0.x, aj0.y, aj0.z, aj0.w, aj1.x, aj1.y, aj1.z, aj1.w};
        float p[8];
        #pragma unroll
        for (int c = 0; c < 8; c++) {
            float x = xs[c];
            float e = fmaxf(x, ALPHA * x);
            e = (am[c] > 0) ? e : NEG_INF;
            p[c] = exp2f(fmaf(e, L2E, -mt2));
        }
        __half2 h0 = __floats2half2_rn(p[0], p[1]);
        __half2 h1 = __floats2half2_rn(p[2], p[3]);
        __half2 h2 = __floats2half2_rn(p[4], p[5]);
        __half2 h3 = __floats2half2_rn(p[6], p[7]);
        uint4 v;
        v.x = *(uint32_t*)&h0; v.y = *(uint32_t*)&h1;
        v.z = *(uint32_t*)&h2; v.w = *(uint32_t*)&h3;
        *(uint4*)&psm[0][rb * 80 + (t & 3) * 16] = v;
    }
    // prefetch adj tile 1
    aj0 = *(const int4*)&adjrow[KT];
    aj1 = *(const int4*)&adjrow[KT + 4];

    for (int it = 0; it < NIT; ++it) {
        int cur = it & 1;
        int nxt = cur ^ 1;
        bool more = (it + 1 < NIT);

        cp_wait<0>();
        __syncthreads();   // publishes stage cur; retires all reads of nxt

        if (more) {
            int kn = (it + 1) * KT;
            // Wh[nxt]
            cp_async16(wh_dst + nxt * 8192, wh_src + (size_t)kn * DOUT);
            cp_async16(wh_dst + nxt * 8192 + 128, wh_src + (size_t)kn * DOUT + 64);
            cp_commit();

            // build P[nxt] (tile it+1)
            {
                float4 d0 = *(const float4*)&g_dst[kn + kc8];
                float4 d1 = *(const float4*)&g_dst[kn + kc8 + 4];
                float xs[8] = {sv + d0.x, sv + d0.y, sv + d0.z, sv + d0.w,
                               sv + d1.x, sv + d1.y, sv + d1.z, sv + d1.w};
                int   am[8] = {aj0.x, aj0.y, aj0.z, aj0.w,
                               aj1.x, aj1.y, aj1.z, aj1.w};
                float p[8];
                #pragma unroll
                for (int c = 0; c < 8; c++) {
                    float x = xs[c];
                    float e = fmaxf(x, ALPHA * x);
                    e = (am[c] > 0) ? e : NEG_INF;
                    p[c] = exp2f(fmaf(e, L2E, -mt2));
                }
                __half2 h0 = __floats2half2_rn(p[0], p[1]);
                __half2 h1 = __floats2half2_rn(p[2], p[3]);
                __half2 h2 = __floats2half2_rn(p[4], p[5]);
                __half2 h3 = __floats2half2_rn(p[6], p[7]);
                uint4 v;
                v.x = *(uint32_t*)&h0; v.y = *(uint32_t*)&h1;
                v.z = *(uint32_t*)&h2; v.w = *(uint32_t*)&h3;
                *(uint4*)&psm[nxt][rb * 80 + (t & 3) * 16] = v;
            }

            // prefetch adj for tile it+2
            if (it + 2 < NIT) {
                const int* ab = adjrow + (it + 2) * KT;
                aj0 = *(const int4*)&ab[0];
                aj1 = *(const int4*)&ab[4];
            }
        }

        // ---- MMA on stage cur: warp tile 32 rows x 32 cols ----
        {
            uint32_t aA = aAddr0 + cur * 5120;
            uint32_t bA0 = bAddr0 + cur * 8192;
            uint32_t bA1 = bAddr1 + cur * 8192;
            #pragma unroll
            for (int ks = 0; ks < 2; ks++) {
                uint32_t b0[4], b1[4];
                ldmx4t(b0, bA0 + ks * 4096);   // cols nj*32+0..15, k 16
                ldmx4t(b1, bA1 + ks * 4096);   // cols nj*32+16..31
                #pragma unroll
                for (int itile = 0; itile < 2; itile++) {
                    uint32_t a[4];
                    ldmx4(a, aA + itile * 1280 + ks * 32);
                    mma16816(acc[itile][0], a, b0[0], b0[1]);
                    mma16816(acc[itile][1], a, b0[2], b0[3]);
                    mma16816(acc[itile][2], a, b1[0], b1[1]);
                    mma16816(acc[itile][3], a, b1[2], b1[3]);
                }
            }
        }
    }

    // ---- epilogue: /rowsum, ELU, store ----
    #pragma unroll
    for (int itile = 0; itile < 2; itile++) {
        int r0 = mi * 32 + itile * 16 + (lane >> 2);
        float l0 = linv_s[r0], l1 = linv_s[r0 + 8];
        #pragma unroll
        for (int nb = 0; nb < 4; nb++) {
            int c = J0 + nj * 32 + nb * 8 + (lane & 3) * 2;
            float v0 = acc[itile][nb][0] * l0;
            float v1 = acc[itile][nb][1] * l0;
            float v2 = acc[itile][nb][2] * l1;
            float v3 = acc[itile][nb][3] * l1;
            float2 lo, hi;
            lo.x = (v0 > 0.f) ? v0 : expm1f(v0);
            lo.y = (v1 > 0.f) ? v1 : expm1f(v1);
            hi.x = (v2 > 0.f) ? v2 : expm1f(v2);
            hi.y = (v3 > 0.f) ? v3 : expm1f(v3);
            *(float2*)&out[(size_t)(I0 + r0)     * DOUT + c] = lo;
            *(float2*)&out[(size_t)(I0 + r0 + 8) * DOUT + c] = hi;
        }
    }
}

// ---------------- launch ------------------------------------------------------
extern "C" void kernel_launch(void* const* d_in, const int* in_sizes, int n_in,
                              void* d_out, int out_size) {
    const float* X   = (const float*)d_in[0];   // features [8192,512]
    const int*   adj = (const int*)  d_in[1];   // adj      [8192,8192]
    const float* W   = (const float*)d_in[2];   // W        [512,256]
    const float* a   = (const float*)d_in[3];   // a        [512,1]
    float* out = (float*)d_out;                 // [8192,256]

    k1_gemm    <<<dim3(N_NODES / 64, DOUT / 64), 256>>>(X, W);
    k2_srcdst  <<<N_NODES / 8, 256>>>(a);
    k3_rowstats<<<N_NODES, 256>>>(adj);
    k4_attn    <<<dim3(DOUT / 128, N_NODES / 64), 256>>>(adj, out);
}